// round 12
// baseline (speedup 1.0000x reference)
#include <cuda_runtime.h>
#include <math.h>

// ---------------------------------------------------------------------------
// Mesh rasterizer — z-sorted stream + tile filter + fast-z reject
//   + cross-split shared per-pixel z bound + within-chunk group suffix-min break.
// Output (float32): [pix_feats npix*C][p2f npix][zbuf npix][bary 3npix][dists npix]
// ---------------------------------------------------------------------------

#define FMAX     32768
#define PIXMAX   65536
#define TILE     16
#define NBUCK    1024
#define CHK      256
#define NGRP     (CHK / 32)       // 8
#define NCHMAX   (FMAX / CHK)     // 128
#define NSPLIT   8

// fixed bucket mapping (perf-tuned to scene z range; correctness range-free)
#define ZB_LO    2.0f
#define ZB_W     (3.0f / (float)NBUCK)
#define ZB_SCALE ((float)NBUCK / 3.0f)

// per-face packed records (original face id order)
// pa=(x0,y0,z0,inva) pb=(x1,y1,z1,z0*z1) pc=(x2,y2,z2,zskip) pd=(bxmin,bxmax,bymin,bymax)
__device__ float4 g_pa[FMAX], g_pb[FMAX], g_pc[FMAX], g_pd[FMAX];

// z-sorted compacted valid faces
__device__ float4 o_pa[FMAX], o_pb[FMAX], o_pc[FMAX], o_pd[FMAX];
__device__ int    o_fid[FMAX];

__device__ int      g_hist[NBUCK];      // zero at load; re-zeroed by k_mf
__device__ int      g_boff[NBUCK];
__device__ int      g_nvalid;
__device__ float    g_chsuf[NCHMAX];

__device__ unsigned g_zshared[PIXMAX];  // cross-split per-pixel z bound (f2o)
__device__ float g_pz[NSPLIT * PIXMAX];
__device__ int   g_pidx[NSPLIT * PIXMAX];

__device__ __forceinline__ float f_inf() { return __int_as_float(0x7f800000); }

__device__ __forceinline__ unsigned f2o(float f) {
    unsigned u = __float_as_uint(f);
    return (u & 0x80000000u) ? ~u : (u | 0x80000000u);
}
__device__ __forceinline__ float o2f(unsigned u) {
    unsigned v = (u & 0x80000000u) ? (u & 0x7fffffffu) : ~u;
    return __uint_as_float(v);
}

__device__ __forceinline__ int bucket_of(float z)
{
    int b = (int)(__fmul_rn(__fsub_rn(z, ZB_LO), ZB_SCALE));
    if (b < 0) b = 0;
    if (b > NBUCK - 1) b = NBUCK - 1;
    return b;
}

// vertex transform (bit-identical to reference sequence)
__device__ __forceinline__ void xform_vertex(
    const float* __restrict__ pos, const float* __restrict__ K,
    const float* __restrict__ RT, int v, float Wf, float Hf,
    float& ox, float& oy, float& oz)
{
    float x = pos[3 * v + 0], y = pos[3 * v + 1], z = pos[3 * v + 2];
    float vv[3];
#pragma unroll
    for (int j = 0; j < 3; j++) {
        float sg = (j == 2) ? 1.0f : -1.0f;
        float Rp0 = __fmul_rn(RT[j * 4 + 0], sg);
        float Rp1 = __fmul_rn(RT[j * 4 + 1], sg);
        float Rp2 = __fmul_rn(RT[j * 4 + 2], sg);
        float Tp  = __fmul_rn(RT[j * 4 + 3], sg);
        float a = __fmul_rn(x, Rp0);
        a = __fadd_rn(a, __fmul_rn(y, Rp1));
        a = __fadd_rn(a, __fmul_rn(z, Rp2));
        vv[j] = __fadd_rn(a, Tp);
    }
    float scale = __fmul_rn(fminf(Hf, Wf), 0.5f);
    float fx = __fdiv_rn(K[0], scale);
    float fy = __fdiv_rn(K[4], scale);
    float p0x = -__fdiv_rn(__fsub_rn(K[2], __fmul_rn(Wf, 0.5f)), scale);
    float p0y = -__fdiv_rn(__fsub_rn(K[5], __fmul_rn(Hf, 0.5f)), scale);
    float zz = vv[2];
    ox = __fadd_rn(__fdiv_rn(__fmul_rn(fx, vv[0]), zz), p0x);
    oy = __fadd_rn(__fdiv_rn(__fmul_rn(fy, vv[1]), zz), p0y);
    oz = zz;
}

// ------------------ face precompute (fused vertex + hist + zshared init) ---
__global__ void k_face(const float* __restrict__ pos,
                       const float* __restrict__ K,
                       const float* __restrict__ RT,
                       const int* __restrict__ faces,
                       int Fn, int npix, float Wf, float Hf)
{
    for (int p = blockIdx.x * blockDim.x + threadIdx.x; p < npix;
         p += gridDim.x * blockDim.x)
        g_zshared[p] = 0xFFFFFFFFu;    // +inf ordered

    int f = blockIdx.x * blockDim.x + threadIdx.x;
    if (f >= Fn) return;

    int i0 = faces[3 * f + 0], i1 = faces[3 * f + 1], i2 = faces[3 * f + 2];
    float x0, y0, z0, x1, y1, z1, x2, y2, z2;
    xform_vertex(pos, K, RT, i0, Wf, Hf, x0, y0, z0);
    xform_vertex(pos, K, RT, i1, Wf, Hf, x1, y1, z1);
    xform_vertex(pos, K, RT, i2, Wf, Hf, x2, y2, z2);

    float area = __fsub_rn(__fmul_rn(__fsub_rn(x1, x0), __fsub_rn(y2, y0)),
                           __fmul_rn(__fsub_rn(y1, y0), __fsub_rn(x2, x0)));
    bool ok = (area > 1e-8f) && (z0 > 0.0f) && (z1 > 0.0f) && (z2 > 0.0f);
    float inva = ok ? __fdiv_rn(1.0f, area) : 0.0f;

    float zmn = fminf(z0, fminf(z1, z2));
    float zskip = zmn - 1e-4f;
    const float M = 5e-3f;
    g_pa[f] = make_float4(x0, y0, z0, inva);
    g_pb[f] = make_float4(x1, y1, z1, __fmul_rn(z0, z1));
    g_pc[f] = make_float4(x2, y2, z2, zskip);
    g_pd[f] = make_float4(fminf(x0, fminf(x1, x2)) - M,
                          fmaxf(x0, fmaxf(x1, x2)) + M,
                          fminf(y0, fminf(y1, y2)) - M,
                          fmaxf(y0, fmaxf(y1, y2)) + M);

    if (ok) atomicAdd(&g_hist[bucket_of(zskip)], 1);
}

// ------------------ scan (warp-shuffle) + chunk suffix z bound -------------
__global__ void k_scan()   // 1 block, NBUCK threads
{
    __shared__ int cum[NBUCK];
    __shared__ int wsum[NBUCK / 32];
    int t = threadIdx.x, lane = t & 31, wid = t >> 5;
    int v = g_hist[t];
    int incl = v;
#pragma unroll
    for (int off = 1; off < 32; off <<= 1) {
        int nb = __shfl_up_sync(0xffffffffu, incl, off);
        if (lane >= off) incl += nb;
    }
    if (lane == 31) wsum[wid] = incl;
    __syncthreads();
    if (wid == 0) {
        int s = wsum[lane];
#pragma unroll
        for (int off = 1; off < 32; off <<= 1) {
            int nb = __shfl_up_sync(0xffffffffu, s, off);
            if (lane >= off) s += nb;
        }
        wsum[lane] = s;
    }
    __syncthreads();
    int prefix = (wid > 0) ? wsum[wid - 1] : 0;
    int ci = incl + prefix;
    cum[t] = ci;
    g_boff[t] = ci - v;
    __syncthreads();

    int total = cum[NBUCK - 1];
    if (t == NBUCK - 1) g_nvalid = total;

    if (t < NCHMAX) {
        int pos = t * CHK;
        float suf;
        if (pos >= total) {
            suf = f_inf();
        } else {
            int lo = 0, hi = NBUCK - 1;
            while (lo < hi) {
                int mid = (lo + hi) >> 1;
                if (cum[mid] > pos) hi = mid; else lo = mid + 1;
            }
            suf = (lo == 0) ? (-1e-4f - 1e-5f)
                            : (ZB_LO + ZB_W * (float)lo - 1e-5f);
        }
        g_chsuf[t] = suf;
    }
}

__global__ void k_scatter(int Fn)
{
    int f = blockIdx.x * blockDim.x + threadIdx.x;
    if (f >= Fn) return;
    if (g_pa[f].w <= 0.0f) return;
    float zs = g_pc[f].w;
    int b = bucket_of(zs);
    int p = atomicAdd(&g_boff[b], 1);
    o_pa[p] = g_pa[f]; o_pb[p] = g_pb[f]; o_pc[p] = g_pc[f]; o_pd[p] = g_pd[f];
    o_fid[p] = f;
}

// ------------------------- exact bary (reference op order) -----------------
__device__ __forceinline__ void eval_exact(
    float px, float py,
    float x0, float y0, float z0, float x1, float y1, float z1,
    float x2, float y2, float z2, float inva, float z01,
    bool& inside, float& zpix, float& d0, float& d1, float& d2)
{
    float dx0 = __fsub_rn(x0, px), dy0 = __fsub_rn(y0, py);
    float dx1 = __fsub_rn(x1, px), dy1 = __fsub_rn(y1, py);
    float dx2 = __fsub_rn(x2, px), dy2 = __fsub_rn(y2, py);
    float w0 = __fmul_rn(__fsub_rn(__fmul_rn(dx1, dy2), __fmul_rn(dy1, dx2)), inva);
    float w1 = __fmul_rn(__fsub_rn(__fmul_rn(dx2, dy0), __fmul_rn(dy2, dx0)), inva);
    float w2 = __fmul_rn(__fsub_rn(__fmul_rn(dx0, dy1), __fmul_rn(dy0, dx1)), inva);
    inside = (w0 >= 0.0f) && (w1 >= 0.0f) && (w2 >= 0.0f);
    if (!inside) { zpix = f_inf(); d0 = d1 = d2 = 0.0f; return; }
    float l0 = __fmul_rn(__fmul_rn(w0, z1), z2);
    float l1 = __fmul_rn(__fmul_rn(z0, w1), z2);
    float l2 = __fmul_rn(z01, w2);
    float s  = __fadd_rn(__fadd_rn(l0, l1), l2);
    float sden = (s == 0.0f) ? 1.0f : s;
    float b0 = __fdiv_rn(l0, sden);
    float b1 = __fdiv_rn(l1, sden);
    float b2 = __fdiv_rn(l2, sden);
    b0 = fmaxf(b0, 0.0f); b1 = fmaxf(b1, 0.0f); b2 = fmaxf(b2, 0.0f);
    float sb = __fadd_rn(__fadd_rn(b0, b1), b2);
    float den2 = fmaxf(sb, 1e-8f);
    d0 = __fdiv_rn(b0, den2);
    d1 = __fdiv_rn(b1, den2);
    d2 = __fdiv_rn(b2, den2);
    zpix = __fadd_rn(__fadd_rn(__fmul_rn(d0, z0), __fmul_rn(d1, z1)),
                     __fmul_rn(d2, z2));
}

// ------------------------- fused raster (shared z bound) -------------------
__global__ void __launch_bounds__(256) k_raster(int W, int H, int npix, int tilesX)
{
    __shared__ float4 sa[CHK], sb[CHK], sc[CHK], sd[CHK];
    __shared__ float  szs[CHK];
    __shared__ int    sfid[CHK];
    __shared__ float  sgmin[NGRP];
    __shared__ float  sgsuf[NGRP];
    __shared__ int    scnt;

    int tile = blockIdx.x;
    int split = blockIdx.y;
    int tx = tile % tilesX, ty = tile / tilesX;
    int lx = threadIdx.x & (TILE - 1), ly = threadIdx.x / TILE;
    int j = tx * TILE + lx, i = ty * TILE + ly;
    bool live = (j < W) && (i < H);
    int pix = live ? (i * W + j) : 0;

    float px = 0.0f, py = 0.0f;
    if (live) {
        px = __fsub_rn(1.0f, __fdiv_rn(__fadd_rn(__fmul_rn(2.0f, (float)j), 1.0f), (float)W));
        py = __fsub_rn(1.0f, __fdiv_rn(__fadd_rn(__fmul_rn(2.0f, (float)i), 1.0f), (float)H));
    }
    // tile ndc rect (px decreasing in j, py decreasing in i)
    int jlo = tx * TILE, jhi = min(W - 1, tx * TILE + TILE - 1);
    int ilo = ty * TILE, ihi = min(H - 1, ty * TILE + TILE - 1);
    float pxHi = __fsub_rn(1.0f, __fdiv_rn(__fadd_rn(__fmul_rn(2.0f, (float)jlo), 1.0f), (float)W));
    float pxLo = __fsub_rn(1.0f, __fdiv_rn(__fadd_rn(__fmul_rn(2.0f, (float)jhi), 1.0f), (float)W));
    float pyHi = __fsub_rn(1.0f, __fdiv_rn(__fadd_rn(__fmul_rn(2.0f, (float)ilo), 1.0f), (float)H));
    float pyLo = __fsub_rn(1.0f, __fdiv_rn(__fadd_rn(__fmul_rn(2.0f, (float)ihi), 1.0f), (float)H));

    int n = g_nvalid;
    int nch = (n + CHK - 1) / CHK;
    float bestZ = f_inf();   // local winner z (exact)
    int   bestI = -1;
    int lane = threadIdx.x & 31;

    for (int c = split; c < nch; c += NSPLIT) {
        // cross-split shared bound (L2-fresh; stale only ever conservative)
        float bound = bestZ;
        if (live) bound = fminf(bound, o2f(__ldcg(&g_zshared[pix])));

        int done = (!live) || (g_chsuf[c] >= bound);
        if (__syncthreads_and(done)) break;

        if (threadIdx.x == 0) scnt = 0;
        __syncthreads();

        int base = c * CHK;
        int cnt = min(CHK, n - base);
        int t = threadIdx.x;
        bool keep = false;
        float4 d;
        int g = base + t;
        if (t < cnt) {
            d = o_pd[g];
            keep = (d.x <= pxHi) && (d.y >= pxLo) && (d.z <= pyHi) && (d.w >= pyLo);
        }
        unsigned m = __ballot_sync(0xffffffffu, keep);
        int nw = __popc(m);
        int bw = 0;
        if (lane == 0 && nw) bw = atomicAdd(&scnt, nw);
        bw = __shfl_sync(0xffffffffu, bw, 0);
        if (keep) {
            int pos = bw + __popc(m & ((1u << lane) - 1u));
            sa[pos] = o_pa[g]; sb[pos] = o_pb[g];
            float4 cc = o_pc[g];
            sc[pos] = cc; szs[pos] = cc.w;
            sd[pos] = d; sfid[pos] = o_fid[g];
        }
        __syncthreads();
        int ns = scnt;
        int ngrp = (ns + 31) >> 5;
        // group minima (parallel) + suffix-min over groups (serial, <=8)
        if ((int)threadIdx.x < ngrp) {
            float mn = f_inf();
            int s0 = threadIdx.x << 5, e0 = min(ns, s0 + 32);
            for (int k = s0; k < e0; k++) mn = fminf(mn, szs[k]);
            sgmin[threadIdx.x] = mn;
        }
        __syncthreads();
        if (threadIdx.x == 0) {
            float suf = f_inf();
            for (int gq = ngrp - 1; gq >= 0; gq--) {
                suf = fminf(suf, sgmin[gq]);
                sgsuf[gq] = suf;
            }
        }
        __syncthreads();

        if (live && !done) {
            for (int gq = 0; gq < ngrp; gq++) {
                if (sgsuf[gq] >= bound) break;    // all remaining zskip >= bound
                int kend = min(ns, (gq << 5) + 32);
                for (int k = gq << 5; k < kend; k++) {
                    if (szs[k] >= bound) continue;            // conservative z cull
                    float4 dd = sd[k];
                    if (px < dd.x || px > dd.y || py < dd.z || py > dd.w) continue;
                    float4 a = sa[k], b = sb[k], cc = sc[k];

                    // inside test (no divisions; identical op order to exact path)
                    float dx0 = __fsub_rn(a.x, px), dy0 = __fsub_rn(a.y, py);
                    float dx1 = __fsub_rn(b.x, px), dy1 = __fsub_rn(b.y, py);
                    float dx2 = __fsub_rn(cc.x, px), dy2 = __fsub_rn(cc.y, py);
                    float w0 = __fmul_rn(__fsub_rn(__fmul_rn(dx1, dy2), __fmul_rn(dy1, dx2)), a.w);
                    float w1 = __fmul_rn(__fsub_rn(__fmul_rn(dx2, dy0), __fmul_rn(dy2, dx0)), a.w);
                    float w2 = __fmul_rn(__fsub_rn(__fmul_rn(dx0, dy1), __fmul_rn(dy0, dx1)), a.w);
                    if (!((w0 >= 0.0f) && (w1 >= 0.0f) && (w2 >= 0.0f))) continue;

                    float l0 = __fmul_rn(__fmul_rn(w0, b.z), cc.z);
                    float l1 = __fmul_rn(__fmul_rn(a.z, w1), cc.z);
                    float l2 = __fmul_rn(b.w, w2);
                    float s  = __fadd_rn(__fadd_rn(l0, l1), l2);

                    // fast approximate z reject (|zfast - zexact| ~5e-6 << 1e-4)
                    if (s > 1e-30f) {
                        float num = l0 * a.z + l1 * b.z + l2 * cc.z;
                        float zfast = __fdividef(num, s);
                        if (zfast > bound + 1e-4f) continue;
                        // refresh bound from L2 before paying for the exact path
                        bound = fminf(bound, o2f(__ldcg(&g_zshared[pix])));
                        if (zfast > bound + 1e-4f) continue;
                    }

                    // exact path (reference op order), reusing identical l/s
                    float sden = (s == 0.0f) ? 1.0f : s;
                    float b0 = __fdiv_rn(l0, sden);
                    float b1 = __fdiv_rn(l1, sden);
                    float b2 = __fdiv_rn(l2, sden);
                    b0 = fmaxf(b0, 0.0f); b1 = fmaxf(b1, 0.0f); b2 = fmaxf(b2, 0.0f);
                    float sb2 = __fadd_rn(__fadd_rn(b0, b1), b2);
                    float den2 = fmaxf(sb2, 1e-8f);
                    float d0 = __fdiv_rn(b0, den2);
                    float d1 = __fdiv_rn(b1, den2);
                    float d2 = __fdiv_rn(b2, den2);
                    float zpix = __fadd_rn(__fadd_rn(__fmul_rn(d0, a.z), __fmul_rn(d1, b.z)),
                                           __fmul_rn(d2, cc.z));

                    int idx = sfid[k];
                    if (zpix < bestZ || (zpix == bestZ && idx < bestI)) {
                        bestZ = zpix; bestI = idx;
                        bound = fminf(bound, bestZ);
                        atomicMin(&g_zshared[pix], f2o(zpix));   // publish
                    }
                }
            }
        }
    }
    if (live) {
        g_pz[split * npix + pix]   = bestZ;
        g_pidx[split * npix + pix] = bestI;
    }
}

// ------------------------- merge + feats (fused, warp/pixel) ---------------
__global__ void k_mf(float* __restrict__ out,
                     const float* __restrict__ feats,
                     const int* __restrict__ faces,
                     int W, int H, int npix, int C)
{
    if (blockIdx.x == 0) {
        for (int t = threadIdx.x; t < NBUCK; t += blockDim.x) g_hist[t] = 0;
    }

    int gw = (blockIdx.x * blockDim.x + threadIdx.x) >> 5;
    int lane = threadIdx.x & 31;
    if (gw >= npix) return;

    int bi = -1;
    float e0 = 0.0f, e1 = 0.0f, e2 = 0.0f;

    if (lane == 0) {
        float bz = f_inf();
#pragma unroll
        for (int sp = 0; sp < NSPLIT; sp++) {
            float z = g_pz[sp * npix + gw];
            int  id = g_pidx[sp * npix + gw];
            if (id >= 0 && (z < bz || (z == bz && id < bi))) { bz = z; bi = id; }
        }

        float p2f, zb, ba0, ba1, ba2, ds;
        if (bi < 0) {
            p2f = -1.0f; zb = -1.0f; ba0 = ba1 = ba2 = -1.0f; ds = -1.0f;
        } else {
            int i = gw / W, j = gw % W;
            float px = __fsub_rn(1.0f, __fdiv_rn(__fadd_rn(__fmul_rn(2.0f, (float)j), 1.0f), (float)W));
            float py = __fsub_rn(1.0f, __fdiv_rn(__fadd_rn(__fmul_rn(2.0f, (float)i), 1.0f), (float)H));
            float4 a = g_pa[bi], b = g_pb[bi], c = g_pc[bi];
            bool inside; float zpix;
            eval_exact(px, py, a.x, a.y, a.z, b.x, b.y, b.z, c.x, c.y, c.z,
                       a.w, b.w, inside, zpix, e0, e1, e2);
            p2f = (float)bi; zb = bz; ba0 = e0; ba1 = e1; ba2 = e2; ds = 0.0f;
        }
        size_t o1 = (size_t)npix * (size_t)C;
        out[o1 + gw] = p2f;
        out[o1 + npix + gw] = zb;
        out[o1 + 2 * (size_t)npix + 3 * (size_t)gw + 0] = ba0;
        out[o1 + 2 * (size_t)npix + 3 * (size_t)gw + 1] = ba1;
        out[o1 + 2 * (size_t)npix + 3 * (size_t)gw + 2] = ba2;
        out[o1 + 5 * (size_t)npix + gw] = ds;
    }

    bi = __shfl_sync(0xffffffffu, bi, 0);
    float* o = out + (size_t)gw * (size_t)C;
    if (bi < 0) {
        if ((C & 1) == 0) {
            float2* o2 = (float2*)o;
            for (int c = lane; c < C / 2; c += 32) o2[c] = make_float2(0.0f, 0.0f);
        } else {
            for (int c = lane; c < C; c += 32) o[c] = 0.0f;
        }
        return;
    }
    e0 = __shfl_sync(0xffffffffu, e0, 0);
    e1 = __shfl_sync(0xffffffffu, e1, 0);
    e2 = __shfl_sync(0xffffffffu, e2, 0);

    int v0 = faces[3 * bi + 0], v1 = faces[3 * bi + 1], v2 = faces[3 * bi + 2];
    const float* f0 = feats + (size_t)v0 * (size_t)C;
    const float* f1 = feats + (size_t)v1 * (size_t)C;
    const float* f2 = feats + (size_t)v2 * (size_t)C;
    if ((C & 1) == 0) {
        const float2* f02 = (const float2*)f0;
        const float2* f12 = (const float2*)f1;
        const float2* f22 = (const float2*)f2;
        float2* o2 = (float2*)o;
        for (int c = lane; c < C / 2; c += 32) {
            float2 a = f02[c], b = f12[c], d = f22[c];
            float vx = __fadd_rn(__fadd_rn(__fmul_rn(e0, a.x), __fmul_rn(e1, b.x)),
                                 __fmul_rn(e2, d.x));
            float vy = __fadd_rn(__fadd_rn(__fmul_rn(e0, a.y), __fmul_rn(e1, b.y)),
                                 __fmul_rn(e2, d.y));
            o2[c] = make_float2(vx, vy);
        }
    } else {
        for (int c = lane; c < C; c += 32) {
            float val = __fadd_rn(__fadd_rn(__fmul_rn(e0, f0[c]),
                                            __fmul_rn(e1, f1[c])),
                                  __fmul_rn(e2, f2[c]));
            o[c] = val;
        }
    }
}

// ------------------------- launch -----------------------------------------
extern "C" void kernel_launch(void* const* d_in, const int* in_sizes, int n_in,
                              void* d_out, int out_size)
{
    const float* positions = (const float*)d_in[0];
    const float* features  = (const float*)d_in[1];
    const int*   faces     = (const int*)d_in[2];
    const float* K         = (const float*)d_in[3];
    const float* RT        = (const float*)d_in[4];

    int V  = in_sizes[0] / 3;
    int C  = in_sizes[1] / V;
    int Fn = in_sizes[2] / 3;
    int npix = out_size / (C + 6);
    int W = (int)(sqrt((double)npix) + 0.5);
    if (W <= 0) W = 1;
    int H = npix / W;
    float* out = (float*)d_out;

    int tilesX = (W + TILE - 1) / TILE;
    int tilesY = (H + TILE - 1) / TILE;
    int ntiles = tilesX * tilesY;

    k_face<<<(Fn + 127) / 128, 128>>>(positions, K, RT, faces, Fn, npix,
                                      (float)W, (float)H);
    k_scan<<<1, NBUCK>>>();
    k_scatter<<<(Fn + 127) / 128, 128>>>(Fn);

    dim3 rg(ntiles, NSPLIT);
    k_raster<<<rg, 256>>>(W, H, npix, tilesX);

    k_mf<<<(npix * 32 + 255) / 256, 256>>>(out, features, faces, W, H, npix, C);
}

// round 13
// speedup vs baseline: 1.0632x; 1.0632x over previous
#include <cuda_runtime.h>
#include <math.h>

// ---------------------------------------------------------------------------
// Mesh rasterizer — z-sorted stream + tile filter + fast-z reject
//                   + cross-split shared per-pixel z bound (fresh-read gating).
// Output (float32): [pix_feats npix*C][p2f npix][zbuf npix][bary 3npix][dists npix]
// ---------------------------------------------------------------------------

#define FMAX     32768
#define PIXMAX   65536
#define TILE     16
#define NBUCK    1024
#define CHK      256
#define NCHMAX   (FMAX / CHK)     // 128
#define NSPLIT   16

// fixed bucket mapping (perf-tuned to scene z range; correctness range-free)
#define ZB_LO    2.0f
#define ZB_W     (3.0f / (float)NBUCK)
#define ZB_SCALE ((float)NBUCK / 3.0f)

// per-face packed records (original face id order)
// pa=(x0,y0,z0,inva) pb=(x1,y1,z1,z0*z1) pc=(x2,y2,z2,zskip) pd=(bxmin,bxmax,bymin,bymax)
__device__ float4 g_pa[FMAX], g_pb[FMAX], g_pc[FMAX], g_pd[FMAX];

// z-sorted compacted valid faces
__device__ float4 o_pa[FMAX], o_pb[FMAX], o_pc[FMAX], o_pd[FMAX];
__device__ int    o_fid[FMAX];

__device__ int      g_hist[NBUCK];      // zero at load; re-zeroed by k_mf
__device__ int      g_boff[NBUCK];
__device__ int      g_nvalid;
__device__ float    g_chsuf[NCHMAX];

__device__ unsigned g_zshared[PIXMAX];  // cross-split per-pixel z bound (f2o)
__device__ float g_pz[NSPLIT * PIXMAX];
__device__ int   g_pidx[NSPLIT * PIXMAX];

__device__ __forceinline__ float f_inf() { return __int_as_float(0x7f800000); }

__device__ __forceinline__ unsigned f2o(float f) {
    unsigned u = __float_as_uint(f);
    return (u & 0x80000000u) ? ~u : (u | 0x80000000u);
}
__device__ __forceinline__ float o2f(unsigned u) {
    unsigned v = (u & 0x80000000u) ? (u & 0x7fffffffu) : ~u;
    return __uint_as_float(v);
}

__device__ __forceinline__ int bucket_of(float z)
{
    int b = (int)(__fmul_rn(__fsub_rn(z, ZB_LO), ZB_SCALE));
    if (b < 0) b = 0;
    if (b > NBUCK - 1) b = NBUCK - 1;
    return b;
}

// vertex transform (bit-identical to reference sequence)
__device__ __forceinline__ void xform_vertex(
    const float* __restrict__ pos, const float* __restrict__ K,
    const float* __restrict__ RT, int v, float Wf, float Hf,
    float& ox, float& oy, float& oz)
{
    float x = pos[3 * v + 0], y = pos[3 * v + 1], z = pos[3 * v + 2];
    float vv[3];
#pragma unroll
    for (int j = 0; j < 3; j++) {
        float sg = (j == 2) ? 1.0f : -1.0f;
        float Rp0 = __fmul_rn(RT[j * 4 + 0], sg);
        float Rp1 = __fmul_rn(RT[j * 4 + 1], sg);
        float Rp2 = __fmul_rn(RT[j * 4 + 2], sg);
        float Tp  = __fmul_rn(RT[j * 4 + 3], sg);
        float a = __fmul_rn(x, Rp0);
        a = __fadd_rn(a, __fmul_rn(y, Rp1));
        a = __fadd_rn(a, __fmul_rn(z, Rp2));
        vv[j] = __fadd_rn(a, Tp);
    }
    float scale = __fmul_rn(fminf(Hf, Wf), 0.5f);
    float fx = __fdiv_rn(K[0], scale);
    float fy = __fdiv_rn(K[4], scale);
    float p0x = -__fdiv_rn(__fsub_rn(K[2], __fmul_rn(Wf, 0.5f)), scale);
    float p0y = -__fdiv_rn(__fsub_rn(K[5], __fmul_rn(Hf, 0.5f)), scale);
    float zz = vv[2];
    ox = __fadd_rn(__fdiv_rn(__fmul_rn(fx, vv[0]), zz), p0x);
    oy = __fadd_rn(__fdiv_rn(__fmul_rn(fy, vv[1]), zz), p0y);
    oz = zz;
}

// ------------------ face precompute (fused vertex + hist + zshared init) ---
__global__ void k_face(const float* __restrict__ pos,
                       const float* __restrict__ K,
                       const float* __restrict__ RT,
                       const int* __restrict__ faces,
                       int Fn, int npix, float Wf, float Hf)
{
    for (int p = blockIdx.x * blockDim.x + threadIdx.x; p < npix;
         p += gridDim.x * blockDim.x)
        g_zshared[p] = 0xFFFFFFFFu;    // +inf ordered

    int f = blockIdx.x * blockDim.x + threadIdx.x;
    if (f >= Fn) return;

    int i0 = faces[3 * f + 0], i1 = faces[3 * f + 1], i2 = faces[3 * f + 2];
    float x0, y0, z0, x1, y1, z1, x2, y2, z2;
    xform_vertex(pos, K, RT, i0, Wf, Hf, x0, y0, z0);
    xform_vertex(pos, K, RT, i1, Wf, Hf, x1, y1, z1);
    xform_vertex(pos, K, RT, i2, Wf, Hf, x2, y2, z2);

    float area = __fsub_rn(__fmul_rn(__fsub_rn(x1, x0), __fsub_rn(y2, y0)),
                           __fmul_rn(__fsub_rn(y1, y0), __fsub_rn(x2, x0)));
    bool ok = (area > 1e-8f) && (z0 > 0.0f) && (z1 > 0.0f) && (z2 > 0.0f);
    float inva = ok ? __fdiv_rn(1.0f, area) : 0.0f;

    float zmn = fminf(z0, fminf(z1, z2));
    float zskip = zmn - 1e-4f;
    const float M = 5e-3f;
    g_pa[f] = make_float4(x0, y0, z0, inva);
    g_pb[f] = make_float4(x1, y1, z1, __fmul_rn(z0, z1));
    g_pc[f] = make_float4(x2, y2, z2, zskip);
    g_pd[f] = make_float4(fminf(x0, fminf(x1, x2)) - M,
                          fmaxf(x0, fmaxf(x1, x2)) + M,
                          fminf(y0, fminf(y1, y2)) - M,
                          fmaxf(y0, fmaxf(y1, y2)) + M);

    if (ok) atomicAdd(&g_hist[bucket_of(zskip)], 1);
}

// ------------------ scan (warp-shuffle) + chunk suffix z bound -------------
__global__ void k_scan()   // 1 block, NBUCK threads
{
    __shared__ int cum[NBUCK];
    __shared__ int wsum[NBUCK / 32];
    int t = threadIdx.x, lane = t & 31, wid = t >> 5;
    int v = g_hist[t];
    int incl = v;
#pragma unroll
    for (int off = 1; off < 32; off <<= 1) {
        int nb = __shfl_up_sync(0xffffffffu, incl, off);
        if (lane >= off) incl += nb;
    }
    if (lane == 31) wsum[wid] = incl;
    __syncthreads();
    if (wid == 0) {
        int s = wsum[lane];
#pragma unroll
        for (int off = 1; off < 32; off <<= 1) {
            int nb = __shfl_up_sync(0xffffffffu, s, off);
            if (lane >= off) s += nb;
        }
        wsum[lane] = s;
    }
    __syncthreads();
    int prefix = (wid > 0) ? wsum[wid - 1] : 0;
    int ci = incl + prefix;
    cum[t] = ci;
    g_boff[t] = ci - v;
    __syncthreads();

    int total = cum[NBUCK - 1];
    if (t == NBUCK - 1) g_nvalid = total;

    if (t < NCHMAX) {
        int pos = t * CHK;
        float suf;
        if (pos >= total) {
            suf = f_inf();
        } else {
            int lo = 0, hi = NBUCK - 1;
            while (lo < hi) {
                int mid = (lo + hi) >> 1;
                if (cum[mid] > pos) hi = mid; else lo = mid + 1;
            }
            suf = (lo == 0) ? (-1e-4f - 1e-5f)
                            : (ZB_LO + ZB_W * (float)lo - 1e-5f);
        }
        g_chsuf[t] = suf;
    }
}

__global__ void k_scatter(int Fn)
{
    int f = blockIdx.x * blockDim.x + threadIdx.x;
    if (f >= Fn) return;
    if (g_pa[f].w <= 0.0f) return;
    float zs = g_pc[f].w;
    int b = bucket_of(zs);
    int p = atomicAdd(&g_boff[b], 1);
    o_pa[p] = g_pa[f]; o_pb[p] = g_pb[f]; o_pc[p] = g_pc[f]; o_pd[p] = g_pd[f];
    o_fid[p] = f;
}

// ------------------------- exact bary (reference op order) -----------------
__device__ __forceinline__ void eval_exact(
    float px, float py,
    float x0, float y0, float z0, float x1, float y1, float z1,
    float x2, float y2, float z2, float inva, float z01,
    bool& inside, float& zpix, float& d0, float& d1, float& d2)
{
    float dx0 = __fsub_rn(x0, px), dy0 = __fsub_rn(y0, py);
    float dx1 = __fsub_rn(x1, px), dy1 = __fsub_rn(y1, py);
    float dx2 = __fsub_rn(x2, px), dy2 = __fsub_rn(y2, py);
    float w0 = __fmul_rn(__fsub_rn(__fmul_rn(dx1, dy2), __fmul_rn(dy1, dx2)), inva);
    float w1 = __fmul_rn(__fsub_rn(__fmul_rn(dx2, dy0), __fmul_rn(dy2, dx0)), inva);
    float w2 = __fmul_rn(__fsub_rn(__fmul_rn(dx0, dy1), __fmul_rn(dy0, dx1)), inva);
    inside = (w0 >= 0.0f) && (w1 >= 0.0f) && (w2 >= 0.0f);
    if (!inside) { zpix = f_inf(); d0 = d1 = d2 = 0.0f; return; }
    float l0 = __fmul_rn(__fmul_rn(w0, z1), z2);
    float l1 = __fmul_rn(__fmul_rn(z0, w1), z2);
    float l2 = __fmul_rn(z01, w2);
    float s  = __fadd_rn(__fadd_rn(l0, l1), l2);
    float sden = (s == 0.0f) ? 1.0f : s;
    float b0 = __fdiv_rn(l0, sden);
    float b1 = __fdiv_rn(l1, sden);
    float b2 = __fdiv_rn(l2, sden);
    b0 = fmaxf(b0, 0.0f); b1 = fmaxf(b1, 0.0f); b2 = fmaxf(b2, 0.0f);
    float sb = __fadd_rn(__fadd_rn(b0, b1), b2);
    float den2 = fmaxf(sb, 1e-8f);
    d0 = __fdiv_rn(b0, den2);
    d1 = __fdiv_rn(b1, den2);
    d2 = __fdiv_rn(b2, den2);
    zpix = __fadd_rn(__fadd_rn(__fmul_rn(d0, z0), __fmul_rn(d1, z1)),
                     __fmul_rn(d2, z2));
}

// ------------------------- fused raster (shared z bound) -------------------
__global__ void __launch_bounds__(256) k_raster(int W, int H, int npix, int tilesX)
{
    __shared__ float4 sa[CHK], sb[CHK], sc[CHK], sd[CHK];
    __shared__ float  szs[CHK];
    __shared__ int    sfid[CHK];
    __shared__ int    scnt;

    int tile = blockIdx.x;
    int split = blockIdx.y;
    int tx = tile % tilesX, ty = tile / tilesX;
    int lx = threadIdx.x & (TILE - 1), ly = threadIdx.x / TILE;
    int j = tx * TILE + lx, i = ty * TILE + ly;
    bool live = (j < W) && (i < H);
    int pix = live ? (i * W + j) : 0;

    float px = 0.0f, py = 0.0f;
    if (live) {
        px = __fsub_rn(1.0f, __fdiv_rn(__fadd_rn(__fmul_rn(2.0f, (float)j), 1.0f), (float)W));
        py = __fsub_rn(1.0f, __fdiv_rn(__fadd_rn(__fmul_rn(2.0f, (float)i), 1.0f), (float)H));
    }
    // tile ndc rect (px decreasing in j, py decreasing in i)
    int jlo = tx * TILE, jhi = min(W - 1, tx * TILE + TILE - 1);
    int ilo = ty * TILE, ihi = min(H - 1, ty * TILE + TILE - 1);
    float pxHi = __fsub_rn(1.0f, __fdiv_rn(__fadd_rn(__fmul_rn(2.0f, (float)jlo), 1.0f), (float)W));
    float pxLo = __fsub_rn(1.0f, __fdiv_rn(__fadd_rn(__fmul_rn(2.0f, (float)jhi), 1.0f), (float)W));
    float pyHi = __fsub_rn(1.0f, __fdiv_rn(__fadd_rn(__fmul_rn(2.0f, (float)ilo), 1.0f), (float)H));
    float pyLo = __fsub_rn(1.0f, __fdiv_rn(__fadd_rn(__fmul_rn(2.0f, (float)ihi), 1.0f), (float)H));

    int n = g_nvalid;
    int nch = (n + CHK - 1) / CHK;
    float bestZ = f_inf();   // local winner z (exact)
    int   bestI = -1;
    int lane = threadIdx.x & 31;

    for (int c = split; c < nch; c += NSPLIT) {
        // cross-split shared bound (L2-fresh; stale only ever conservative)
        float bound = bestZ;
        if (live) bound = fminf(bound, o2f(__ldcg(&g_zshared[pix])));

        int done = (!live) || (g_chsuf[c] >= bound);
        if (__syncthreads_and(done)) break;

        if (threadIdx.x == 0) scnt = 0;
        __syncthreads();

        int base = c * CHK;
        int cnt = min(CHK, n - base);
        int t = threadIdx.x;
        bool keep = false;
        float4 d;
        int g = base + t;
        if (t < cnt) {
            d = o_pd[g];
            keep = (d.x <= pxHi) && (d.y >= pxLo) && (d.z <= pyHi) && (d.w >= pyLo);
        }
        unsigned m = __ballot_sync(0xffffffffu, keep);
        int nw = __popc(m);
        int bw = 0;
        if (lane == 0 && nw) bw = atomicAdd(&scnt, nw);
        bw = __shfl_sync(0xffffffffu, bw, 0);
        if (keep) {
            int pos = bw + __popc(m & ((1u << lane) - 1u));
            sa[pos] = o_pa[g]; sb[pos] = o_pb[g];
            float4 cc = o_pc[g];
            sc[pos] = cc; szs[pos] = cc.w;
            sd[pos] = d; sfid[pos] = o_fid[g];
        }
        __syncthreads();
        int ns = scnt;
        if (live && !done) {
            for (int k = 0; k < ns; k++) {
                if (szs[k] >= bound) continue;                // conservative z cull
                float4 dd = sd[k];
                if (px < dd.x || px > dd.y || py < dd.z || py > dd.w) continue;
                float4 a = sa[k], b = sb[k], cc = sc[k];

                // inside test (no divisions; identical op order to exact path)
                float dx0 = __fsub_rn(a.x, px), dy0 = __fsub_rn(a.y, py);
                float dx1 = __fsub_rn(b.x, px), dy1 = __fsub_rn(b.y, py);
                float dx2 = __fsub_rn(cc.x, px), dy2 = __fsub_rn(cc.y, py);
                float w0 = __fmul_rn(__fsub_rn(__fmul_rn(dx1, dy2), __fmul_rn(dy1, dx2)), a.w);
                float w1 = __fmul_rn(__fsub_rn(__fmul_rn(dx2, dy0), __fmul_rn(dy2, dx0)), a.w);
                float w2 = __fmul_rn(__fsub_rn(__fmul_rn(dx0, dy1), __fmul_rn(dy0, dx1)), a.w);
                if (!((w0 >= 0.0f) && (w1 >= 0.0f) && (w2 >= 0.0f))) continue;

                float l0 = __fmul_rn(__fmul_rn(w0, b.z), cc.z);
                float l1 = __fmul_rn(__fmul_rn(a.z, w1), cc.z);
                float l2 = __fmul_rn(b.w, w2);
                float s  = __fadd_rn(__fadd_rn(l0, l1), l2);

                // fast approximate z reject (|zfast - zexact| ~5e-6 << 1e-4)
                if (s > 1e-30f) {
                    float num = l0 * a.z + l1 * b.z + l2 * cc.z;
                    float zfast = __fdividef(num, s);
                    if (zfast > bound + 1e-4f) continue;
                    // refresh bound from L2 before paying for the exact path
                    bound = fminf(bound, o2f(__ldcg(&g_zshared[pix])));
                    if (zfast > bound + 1e-4f) continue;
                }

                // exact path (reference op order), reusing identical l/s
                float sden = (s == 0.0f) ? 1.0f : s;
                float b0 = __fdiv_rn(l0, sden);
                float b1 = __fdiv_rn(l1, sden);
                float b2 = __fdiv_rn(l2, sden);
                b0 = fmaxf(b0, 0.0f); b1 = fmaxf(b1, 0.0f); b2 = fmaxf(b2, 0.0f);
                float sb2 = __fadd_rn(__fadd_rn(b0, b1), b2);
                float den2 = fmaxf(sb2, 1e-8f);
                float d0 = __fdiv_rn(b0, den2);
                float d1 = __fdiv_rn(b1, den2);
                float d2 = __fdiv_rn(b2, den2);
                float zpix = __fadd_rn(__fadd_rn(__fmul_rn(d0, a.z), __fmul_rn(d1, b.z)),
                                       __fmul_rn(d2, cc.z));

                int idx = sfid[k];
                if (zpix < bestZ || (zpix == bestZ && idx < bestI)) {
                    bestZ = zpix; bestI = idx;
                    bound = fminf(bound, bestZ);
                    atomicMin(&g_zshared[pix], f2o(zpix));   // publish
                }
            }
        }
    }
    if (live) {
        g_pz[split * npix + pix]   = bestZ;
        g_pidx[split * npix + pix] = bestI;
    }
}

// ------------------------- merge + feats (fused, warp/pixel) ---------------
__global__ void k_mf(float* __restrict__ out,
                     const float* __restrict__ feats,
                     const int* __restrict__ faces,
                     int W, int H, int npix, int C)
{
    if (blockIdx.x == 0) {
        for (int t = threadIdx.x; t < NBUCK; t += blockDim.x) g_hist[t] = 0;
    }

    int gw = (blockIdx.x * blockDim.x + threadIdx.x) >> 5;
    int lane = threadIdx.x & 31;
    if (gw >= npix) return;

    int bi = -1;
    float e0 = 0.0f, e1 = 0.0f, e2 = 0.0f;

    if (lane == 0) {
        float bz = f_inf();
#pragma unroll
        for (int sp = 0; sp < NSPLIT; sp++) {
            float z = g_pz[sp * npix + gw];
            int  id = g_pidx[sp * npix + gw];
            if (id >= 0 && (z < bz || (z == bz && id < bi))) { bz = z; bi = id; }
        }

        float p2f, zb, ba0, ba1, ba2, ds;
        if (bi < 0) {
            p2f = -1.0f; zb = -1.0f; ba0 = ba1 = ba2 = -1.0f; ds = -1.0f;
        } else {
            int i = gw / W, j = gw % W;
            float px = __fsub_rn(1.0f, __fdiv_rn(__fadd_rn(__fmul_rn(2.0f, (float)j), 1.0f), (float)W));
            float py = __fsub_rn(1.0f, __fdiv_rn(__fadd_rn(__fmul_rn(2.0f, (float)i), 1.0f), (float)H));
            float4 a = g_pa[bi], b = g_pb[bi], c = g_pc[bi];
            bool inside; float zpix;
            eval_exact(px, py, a.x, a.y, a.z, b.x, b.y, b.z, c.x, c.y, c.z,
                       a.w, b.w, inside, zpix, e0, e1, e2);
            p2f = (float)bi; zb = bz; ba0 = e0; ba1 = e1; ba2 = e2; ds = 0.0f;
        }
        size_t o1 = (size_t)npix * (size_t)C;
        out[o1 + gw] = p2f;
        out[o1 + npix + gw] = zb;
        out[o1 + 2 * (size_t)npix + 3 * (size_t)gw + 0] = ba0;
        out[o1 + 2 * (size_t)npix + 3 * (size_t)gw + 1] = ba1;
        out[o1 + 2 * (size_t)npix + 3 * (size_t)gw + 2] = ba2;
        out[o1 + 5 * (size_t)npix + gw] = ds;
    }

    bi = __shfl_sync(0xffffffffu, bi, 0);
    float* o = out + (size_t)gw * (size_t)C;
    if (bi < 0) {
        if ((C & 1) == 0) {
            float2* o2 = (float2*)o;
            for (int c = lane; c < C / 2; c += 32) o2[c] = make_float2(0.0f, 0.0f);
        } else {
            for (int c = lane; c < C; c += 32) o[c] = 0.0f;
        }
        return;
    }
    e0 = __shfl_sync(0xffffffffu, e0, 0);
    e1 = __shfl_sync(0xffffffffu, e1, 0);
    e2 = __shfl_sync(0xffffffffu, e2, 0);

    int v0 = faces[3 * bi + 0], v1 = faces[3 * bi + 1], v2 = faces[3 * bi + 2];
    const float* f0 = feats + (size_t)v0 * (size_t)C;
    const float* f1 = feats + (size_t)v1 * (size_t)C;
    const float* f2 = feats + (size_t)v2 * (size_t)C;
    if ((C & 1) == 0) {
        const float2* f02 = (const float2*)f0;
        const float2* f12 = (const float2*)f1;
        const float2* f22 = (const float2*)f2;
        float2* o2 = (float2*)o;
        for (int c = lane; c < C / 2; c += 32) {
            float2 a = f02[c], b = f12[c], d = f22[c];
            float vx = __fadd_rn(__fadd_rn(__fmul_rn(e0, a.x), __fmul_rn(e1, b.x)),
                                 __fmul_rn(e2, d.x));
            float vy = __fadd_rn(__fadd_rn(__fmul_rn(e0, a.y), __fmul_rn(e1, b.y)),
                                 __fmul_rn(e2, d.y));
            o2[c] = make_float2(vx, vy);
        }
    } else {
        for (int c = lane; c < C; c += 32) {
            float val = __fadd_rn(__fadd_rn(__fmul_rn(e0, f0[c]),
                                            __fmul_rn(e1, f1[c])),
                                  __fmul_rn(e2, f2[c]));
            o[c] = val;
        }
    }
}

// ------------------------- launch -----------------------------------------
extern "C" void kernel_launch(void* const* d_in, const int* in_sizes, int n_in,
                              void* d_out, int out_size)
{
    const float* positions = (const float*)d_in[0];
    const float* features  = (const float*)d_in[1];
    const int*   faces     = (const int*)d_in[2];
    const float* K         = (const float*)d_in[3];
    const float* RT        = (const float*)d_in[4];

    int V  = in_sizes[0] / 3;
    int C  = in_sizes[1] / V;
    int Fn = in_sizes[2] / 3;
    int npix = out_size / (C + 6);
    int W = (int)(sqrt((double)npix) + 0.5);
    if (W <= 0) W = 1;
    int H = npix / W;
    float* out = (float*)d_out;

    int tilesX = (W + TILE - 1) / TILE;
    int tilesY = (H + TILE - 1) / TILE;
    int ntiles = tilesX * tilesY;

    k_face<<<(Fn + 127) / 128, 128>>>(positions, K, RT, faces, Fn, npix,
                                      (float)W, (float)H);
    k_scan<<<1, NBUCK>>>();
    k_scatter<<<(Fn + 127) / 128, 128>>>(Fn);

    dim3 rg(ntiles, NSPLIT);
    k_raster<<<rg, 256>>>(W, H, npix, tilesX);

    k_mf<<<(npix * 32 + 255) / 256, 256>>>(out, features, faces, W, H, npix, C);
}

// round 14
// speedup vs baseline: 1.1719x; 1.1023x over previous
#include <cuda_runtime.h>
#include <math.h>

// ---------------------------------------------------------------------------
// Mesh rasterizer — z-sorted stream + tile filter + fast-z reject
//   + single u64 packed (z,idx) atomicMin winner per pixel (no merge pass).
// Output (float32): [pix_feats npix*C][p2f npix][zbuf npix][bary 3npix][dists npix]
// ---------------------------------------------------------------------------

#define FMAX     32768
#define PIXMAX   65536
#define TILE     16
#define NBUCK    1024
#define CHK      256
#define NCHMAX   (FMAX / CHK)     // 128
#define NSPLIT   16

// fixed bucket mapping (perf-tuned to scene z range; correctness range-free)
#define ZB_LO    2.0f
#define ZB_W     (3.0f / (float)NBUCK)
#define ZB_SCALE ((float)NBUCK / 3.0f)

// per-face packed records (original face id order)
// pa=(x0,y0,z0,inva) pb=(x1,y1,z1,z0*z1) pc=(x2,y2,z2,zskip) pd=(bxmin,bxmax,bymin,bymax)
__device__ float4 g_pa[FMAX], g_pb[FMAX], g_pc[FMAX], g_pd[FMAX];

// z-sorted compacted valid faces
__device__ float4 o_pa[FMAX], o_pb[FMAX], o_pc[FMAX], o_pd[FMAX];
__device__ int    o_fid[FMAX];

__device__ int      g_hist[NBUCK];      // zero at load; re-zeroed by k_mf
__device__ int      g_boff[NBUCK];
__device__ int      g_nvalid;
__device__ float    g_chsuf[NCHMAX];

// packed winner per pixel: (f2o(zpix) << 32) | origFaceIdx  — u64 atomicMin
// == lexicographic (z, idx) min == argmin-first semantics.
__device__ unsigned long long g_zbest[PIXMAX];

__device__ __forceinline__ float f_inf() { return __int_as_float(0x7f800000); }

__device__ __forceinline__ unsigned f2o(float f) {
    unsigned u = __float_as_uint(f);
    return (u & 0x80000000u) ? ~u : (u | 0x80000000u);
}
__device__ __forceinline__ float o2f(unsigned u) {
    unsigned v = (u & 0x80000000u) ? (u & 0x7fffffffu) : ~u;
    return __uint_as_float(v);
}

__device__ __forceinline__ int bucket_of(float z)
{
    int b = (int)(__fmul_rn(__fsub_rn(z, ZB_LO), ZB_SCALE));
    if (b < 0) b = 0;
    if (b > NBUCK - 1) b = NBUCK - 1;
    return b;
}

// vertex transform (bit-identical to reference sequence)
__device__ __forceinline__ void xform_vertex(
    const float* __restrict__ pos, const float* __restrict__ K,
    const float* __restrict__ RT, int v, float Wf, float Hf,
    float& ox, float& oy, float& oz)
{
    float x = pos[3 * v + 0], y = pos[3 * v + 1], z = pos[3 * v + 2];
    float vv[3];
#pragma unroll
    for (int j = 0; j < 3; j++) {
        float sg = (j == 2) ? 1.0f : -1.0f;
        float Rp0 = __fmul_rn(RT[j * 4 + 0], sg);
        float Rp1 = __fmul_rn(RT[j * 4 + 1], sg);
        float Rp2 = __fmul_rn(RT[j * 4 + 2], sg);
        float Tp  = __fmul_rn(RT[j * 4 + 3], sg);
        float a = __fmul_rn(x, Rp0);
        a = __fadd_rn(a, __fmul_rn(y, Rp1));
        a = __fadd_rn(a, __fmul_rn(z, Rp2));
        vv[j] = __fadd_rn(a, Tp);
    }
    float scale = __fmul_rn(fminf(Hf, Wf), 0.5f);
    float fx = __fdiv_rn(K[0], scale);
    float fy = __fdiv_rn(K[4], scale);
    float p0x = -__fdiv_rn(__fsub_rn(K[2], __fmul_rn(Wf, 0.5f)), scale);
    float p0y = -__fdiv_rn(__fsub_rn(K[5], __fmul_rn(Hf, 0.5f)), scale);
    float zz = vv[2];
    ox = __fadd_rn(__fdiv_rn(__fmul_rn(fx, vv[0]), zz), p0x);
    oy = __fadd_rn(__fdiv_rn(__fmul_rn(fy, vv[1]), zz), p0y);
    oz = zz;
}

// ------------------ face precompute (fused vertex + hist + zbest init) -----
__global__ void k_face(const float* __restrict__ pos,
                       const float* __restrict__ K,
                       const float* __restrict__ RT,
                       const int* __restrict__ faces,
                       int Fn, int npix, float Wf, float Hf)
{
    for (int p = blockIdx.x * blockDim.x + threadIdx.x; p < npix;
         p += gridDim.x * blockDim.x)
        g_zbest[p] = 0xFFFFFFFFFFFFFFFFull;

    int f = blockIdx.x * blockDim.x + threadIdx.x;
    if (f >= Fn) return;

    int i0 = faces[3 * f + 0], i1 = faces[3 * f + 1], i2 = faces[3 * f + 2];
    float x0, y0, z0, x1, y1, z1, x2, y2, z2;
    xform_vertex(pos, K, RT, i0, Wf, Hf, x0, y0, z0);
    xform_vertex(pos, K, RT, i1, Wf, Hf, x1, y1, z1);
    xform_vertex(pos, K, RT, i2, Wf, Hf, x2, y2, z2);

    float area = __fsub_rn(__fmul_rn(__fsub_rn(x1, x0), __fsub_rn(y2, y0)),
                           __fmul_rn(__fsub_rn(y1, y0), __fsub_rn(x2, x0)));
    bool ok = (area > 1e-8f) && (z0 > 0.0f) && (z1 > 0.0f) && (z2 > 0.0f);
    float inva = ok ? __fdiv_rn(1.0f, area) : 0.0f;

    float zmn = fminf(z0, fminf(z1, z2));
    float zskip = zmn - 1e-4f;
    const float M = 5e-3f;
    g_pa[f] = make_float4(x0, y0, z0, inva);
    g_pb[f] = make_float4(x1, y1, z1, __fmul_rn(z0, z1));
    g_pc[f] = make_float4(x2, y2, z2, zskip);
    g_pd[f] = make_float4(fminf(x0, fminf(x1, x2)) - M,
                          fmaxf(x0, fmaxf(x1, x2)) + M,
                          fminf(y0, fminf(y1, y2)) - M,
                          fmaxf(y0, fmaxf(y1, y2)) + M);

    if (ok) atomicAdd(&g_hist[bucket_of(zskip)], 1);
}

// ------------------ scan (warp-shuffle) + chunk suffix z bound -------------
__global__ void k_scan()   // 1 block, NBUCK threads
{
    __shared__ int cum[NBUCK];
    __shared__ int wsum[NBUCK / 32];
    int t = threadIdx.x, lane = t & 31, wid = t >> 5;
    int v = g_hist[t];
    int incl = v;
#pragma unroll
    for (int off = 1; off < 32; off <<= 1) {
        int nb = __shfl_up_sync(0xffffffffu, incl, off);
        if (lane >= off) incl += nb;
    }
    if (lane == 31) wsum[wid] = incl;
    __syncthreads();
    if (wid == 0) {
        int s = wsum[lane];
#pragma unroll
        for (int off = 1; off < 32; off <<= 1) {
            int nb = __shfl_up_sync(0xffffffffu, s, off);
            if (lane >= off) s += nb;
        }
        wsum[lane] = s;
    }
    __syncthreads();
    int prefix = (wid > 0) ? wsum[wid - 1] : 0;
    int ci = incl + prefix;
    cum[t] = ci;
    g_boff[t] = ci - v;
    __syncthreads();

    int total = cum[NBUCK - 1];
    if (t == NBUCK - 1) g_nvalid = total;

    if (t < NCHMAX) {
        int pos = t * CHK;
        float suf;
        if (pos >= total) {
            suf = f_inf();
        } else {
            int lo = 0, hi = NBUCK - 1;
            while (lo < hi) {
                int mid = (lo + hi) >> 1;
                if (cum[mid] > pos) hi = mid; else lo = mid + 1;
            }
            suf = (lo == 0) ? (-1e-4f - 1e-5f)
                            : (ZB_LO + ZB_W * (float)lo - 1e-5f);
        }
        g_chsuf[t] = suf;
    }
}

__global__ void k_scatter(int Fn)
{
    int f = blockIdx.x * blockDim.x + threadIdx.x;
    if (f >= Fn) return;
    if (g_pa[f].w <= 0.0f) return;
    float zs = g_pc[f].w;
    int b = bucket_of(zs);
    int p = atomicAdd(&g_boff[b], 1);
    o_pa[p] = g_pa[f]; o_pb[p] = g_pb[f]; o_pc[p] = g_pc[f]; o_pd[p] = g_pd[f];
    o_fid[p] = f;
}

// ------------------------- exact bary (reference op order) -----------------
__device__ __forceinline__ void eval_exact(
    float px, float py,
    float x0, float y0, float z0, float x1, float y1, float z1,
    float x2, float y2, float z2, float inva, float z01,
    bool& inside, float& zpix, float& d0, float& d1, float& d2)
{
    float dx0 = __fsub_rn(x0, px), dy0 = __fsub_rn(y0, py);
    float dx1 = __fsub_rn(x1, px), dy1 = __fsub_rn(y1, py);
    float dx2 = __fsub_rn(x2, px), dy2 = __fsub_rn(y2, py);
    float w0 = __fmul_rn(__fsub_rn(__fmul_rn(dx1, dy2), __fmul_rn(dy1, dx2)), inva);
    float w1 = __fmul_rn(__fsub_rn(__fmul_rn(dx2, dy0), __fmul_rn(dy2, dx0)), inva);
    float w2 = __fmul_rn(__fsub_rn(__fmul_rn(dx0, dy1), __fmul_rn(dy0, dx1)), inva);
    inside = (w0 >= 0.0f) && (w1 >= 0.0f) && (w2 >= 0.0f);
    if (!inside) { zpix = f_inf(); d0 = d1 = d2 = 0.0f; return; }
    float l0 = __fmul_rn(__fmul_rn(w0, z1), z2);
    float l1 = __fmul_rn(__fmul_rn(z0, w1), z2);
    float l2 = __fmul_rn(z01, w2);
    float s  = __fadd_rn(__fadd_rn(l0, l1), l2);
    float sden = (s == 0.0f) ? 1.0f : s;
    float b0 = __fdiv_rn(l0, sden);
    float b1 = __fdiv_rn(l1, sden);
    float b2 = __fdiv_rn(l2, sden);
    b0 = fmaxf(b0, 0.0f); b1 = fmaxf(b1, 0.0f); b2 = fmaxf(b2, 0.0f);
    float sb = __fadd_rn(__fadd_rn(b0, b1), b2);
    float den2 = fmaxf(sb, 1e-8f);
    d0 = __fdiv_rn(b0, den2);
    d1 = __fdiv_rn(b1, den2);
    d2 = __fdiv_rn(b2, den2);
    zpix = __fadd_rn(__fadd_rn(__fmul_rn(d0, z0), __fmul_rn(d1, z1)),
                     __fmul_rn(d2, z2));
}

// ------------------------- fused raster (packed u64 winner) ----------------
__global__ void __launch_bounds__(256) k_raster(int W, int H, int npix, int tilesX)
{
    __shared__ float4 sa[CHK], sb[CHK], sc[CHK], sd[CHK];
    __shared__ float  szs[CHK];
    __shared__ int    sfid[CHK];
    __shared__ int    scnt;

    int tile = blockIdx.x;
    int split = blockIdx.y;
    int tx = tile % tilesX, ty = tile / tilesX;
    int lx = threadIdx.x & (TILE - 1), ly = threadIdx.x / TILE;
    int j = tx * TILE + lx, i = ty * TILE + ly;
    bool live = (j < W) && (i < H);
    int pix = live ? (i * W + j) : 0;

    float px = 0.0f, py = 0.0f;
    if (live) {
        px = __fsub_rn(1.0f, __fdiv_rn(__fadd_rn(__fmul_rn(2.0f, (float)j), 1.0f), (float)W));
        py = __fsub_rn(1.0f, __fdiv_rn(__fadd_rn(__fmul_rn(2.0f, (float)i), 1.0f), (float)H));
    }
    // tile ndc rect (px decreasing in j, py decreasing in i)
    int jlo = tx * TILE, jhi = min(W - 1, tx * TILE + TILE - 1);
    int ilo = ty * TILE, ihi = min(H - 1, ty * TILE + TILE - 1);
    float pxHi = __fsub_rn(1.0f, __fdiv_rn(__fadd_rn(__fmul_rn(2.0f, (float)jlo), 1.0f), (float)W));
    float pxLo = __fsub_rn(1.0f, __fdiv_rn(__fadd_rn(__fmul_rn(2.0f, (float)jhi), 1.0f), (float)W));
    float pyHi = __fsub_rn(1.0f, __fdiv_rn(__fadd_rn(__fmul_rn(2.0f, (float)ilo), 1.0f), (float)H));
    float pyLo = __fsub_rn(1.0f, __fdiv_rn(__fadd_rn(__fmul_rn(2.0f, (float)ihi), 1.0f), (float)H));

    int n = g_nvalid;
    int nch = (n + CHK - 1) / CHK;
    unsigned long long bestPk = 0xFFFFFFFFFFFFFFFFull;   // local cache of packed winner
    int lane = threadIdx.x & 31;

    for (int c = split; c < nch; c += NSPLIT) {
        // refresh local cache from global (stale only ever conservative)
        if (live) {
            unsigned long long gb = __ldcg(&g_zbest[pix]);
            bestPk = min(bestPk, gb);
        }
        float bound = o2f((unsigned)(bestPk >> 32));

        int done = (!live) || (g_chsuf[c] >= bound);
        if (__syncthreads_and(done)) break;

        if (threadIdx.x == 0) scnt = 0;
        __syncthreads();

        int base = c * CHK;
        int cnt = min(CHK, n - base);
        int t = threadIdx.x;
        bool keep = false;
        float4 d;
        int g = base + t;
        if (t < cnt) {
            d = o_pd[g];
            keep = (d.x <= pxHi) && (d.y >= pxLo) && (d.z <= pyHi) && (d.w >= pyLo);
        }
        unsigned m = __ballot_sync(0xffffffffu, keep);
        int nw = __popc(m);
        int bw = 0;
        if (lane == 0 && nw) bw = atomicAdd(&scnt, nw);
        bw = __shfl_sync(0xffffffffu, bw, 0);
        if (keep) {
            int pos = bw + __popc(m & ((1u << lane) - 1u));
            sa[pos] = o_pa[g]; sb[pos] = o_pb[g];
            float4 cc = o_pc[g];
            sc[pos] = cc; szs[pos] = cc.w;
            sd[pos] = d; sfid[pos] = o_fid[g];
        }
        __syncthreads();
        int ns = scnt;
        if (live && !done) {
            for (int k = 0; k < ns; k++) {
                if (szs[k] >= bound) continue;                // conservative z cull
                float4 dd = sd[k];
                if (px < dd.x || px > dd.y || py < dd.z || py > dd.w) continue;
                float4 a = sa[k], b = sb[k], cc = sc[k];

                // inside test (no divisions; identical op order to exact path)
                float dx0 = __fsub_rn(a.x, px), dy0 = __fsub_rn(a.y, py);
                float dx1 = __fsub_rn(b.x, px), dy1 = __fsub_rn(b.y, py);
                float dx2 = __fsub_rn(cc.x, px), dy2 = __fsub_rn(cc.y, py);
                float w0 = __fmul_rn(__fsub_rn(__fmul_rn(dx1, dy2), __fmul_rn(dy1, dx2)), a.w);
                float w1 = __fmul_rn(__fsub_rn(__fmul_rn(dx2, dy0), __fmul_rn(dy2, dx0)), a.w);
                float w2 = __fmul_rn(__fsub_rn(__fmul_rn(dx0, dy1), __fmul_rn(dy0, dx1)), a.w);
                if (!((w0 >= 0.0f) && (w1 >= 0.0f) && (w2 >= 0.0f))) continue;

                float l0 = __fmul_rn(__fmul_rn(w0, b.z), cc.z);
                float l1 = __fmul_rn(__fmul_rn(a.z, w1), cc.z);
                float l2 = __fmul_rn(b.w, w2);
                float s  = __fadd_rn(__fadd_rn(l0, l1), l2);

                // fast approximate z reject (|zfast - zexact| ~5e-6 << 1e-4)
                if (s > 1e-30f) {
                    float num = l0 * a.z + l1 * b.z + l2 * cc.z;
                    float zfast = __fdividef(num, s);
                    if (zfast > bound + 1e-4f) continue;
                    // refresh from L2 before paying for the exact path
                    unsigned long long gb = __ldcg(&g_zbest[pix]);
                    bestPk = min(bestPk, gb);
                    bound = o2f((unsigned)(bestPk >> 32));
                    if (zfast > bound + 1e-4f) continue;
                }

                // exact path (reference op order), reusing identical l/s
                float sden = (s == 0.0f) ? 1.0f : s;
                float b0 = __fdiv_rn(l0, sden);
                float b1 = __fdiv_rn(l1, sden);
                float b2 = __fdiv_rn(l2, sden);
                b0 = fmaxf(b0, 0.0f); b1 = fmaxf(b1, 0.0f); b2 = fmaxf(b2, 0.0f);
                float sb2 = __fadd_rn(__fadd_rn(b0, b1), b2);
                float den2 = fmaxf(sb2, 1e-8f);
                float d0 = __fdiv_rn(b0, den2);
                float d1 = __fdiv_rn(b1, den2);
                float d2 = __fdiv_rn(b2, den2);
                float zpix = __fadd_rn(__fadd_rn(__fmul_rn(d0, a.z), __fmul_rn(d1, b.z)),
                                       __fmul_rn(d2, cc.z));

                unsigned long long pk =
                    ((unsigned long long)f2o(zpix) << 32) | (unsigned)sfid[k];
                if (pk < bestPk) {
                    bestPk = pk;
                    bound = o2f((unsigned)(bestPk >> 32));
                    atomicMin(&g_zbest[pix], pk);            // publish winner
                }
            }
        }
    }
    // no tail writes: winners already published via atomicMin
}

// ------------------------- finalize + feats (warp/pixel) -------------------
__global__ void k_mf(float* __restrict__ out,
                     const float* __restrict__ feats,
                     const int* __restrict__ faces,
                     int W, int H, int npix, int C)
{
    if (blockIdx.x == 0) {
        for (int t = threadIdx.x; t < NBUCK; t += blockDim.x) g_hist[t] = 0;
    }

    int gw = (blockIdx.x * blockDim.x + threadIdx.x) >> 5;
    int lane = threadIdx.x & 31;
    if (gw >= npix) return;

    int bi = -1;
    float e0 = 0.0f, e1 = 0.0f, e2 = 0.0f;

    if (lane == 0) {
        unsigned long long pk = g_zbest[gw];
        unsigned hi = (unsigned)(pk >> 32);
        float p2f, zb, ba0, ba1, ba2, ds;
        if (hi == 0xFFFFFFFFu) {
            bi = -1;
            p2f = -1.0f; zb = -1.0f; ba0 = ba1 = ba2 = -1.0f; ds = -1.0f;
        } else {
            bi = (int)(unsigned)(pk & 0xFFFFFFFFull);
            float bz = o2f(hi);
            int i = gw / W, j = gw % W;
            float px = __fsub_rn(1.0f, __fdiv_rn(__fadd_rn(__fmul_rn(2.0f, (float)j), 1.0f), (float)W));
            float py = __fsub_rn(1.0f, __fdiv_rn(__fadd_rn(__fmul_rn(2.0f, (float)i), 1.0f), (float)H));
            float4 a = g_pa[bi], b = g_pb[bi], c = g_pc[bi];
            bool inside; float zpix;
            eval_exact(px, py, a.x, a.y, a.z, b.x, b.y, b.z, c.x, c.y, c.z,
                       a.w, b.w, inside, zpix, e0, e1, e2);
            p2f = (float)bi; zb = bz; ba0 = e0; ba1 = e1; ba2 = e2; ds = 0.0f;
        }
        size_t o1 = (size_t)npix * (size_t)C;
        out[o1 + gw] = p2f;
        out[o1 + npix + gw] = zb;
        out[o1 + 2 * (size_t)npix + 3 * (size_t)gw + 0] = ba0;
        out[o1 + 2 * (size_t)npix + 3 * (size_t)gw + 1] = ba1;
        out[o1 + 2 * (size_t)npix + 3 * (size_t)gw + 2] = ba2;
        out[o1 + 5 * (size_t)npix + gw] = ds;
    }

    bi = __shfl_sync(0xffffffffu, bi, 0);
    float* o = out + (size_t)gw * (size_t)C;
    if (bi < 0) {
        if ((C & 1) == 0) {
            float2* o2 = (float2*)o;
            for (int c = lane; c < C / 2; c += 32) o2[c] = make_float2(0.0f, 0.0f);
        } else {
            for (int c = lane; c < C; c += 32) o[c] = 0.0f;
        }
        return;
    }
    e0 = __shfl_sync(0xffffffffu, e0, 0);
    e1 = __shfl_sync(0xffffffffu, e1, 0);
    e2 = __shfl_sync(0xffffffffu, e2, 0);

    int v0 = faces[3 * bi + 0], v1 = faces[3 * bi + 1], v2 = faces[3 * bi + 2];
    const float* f0 = feats + (size_t)v0 * (size_t)C;
    const float* f1 = feats + (size_t)v1 * (size_t)C;
    const float* f2 = feats + (size_t)v2 * (size_t)C;
    if ((C & 1) == 0) {
        const float2* f02 = (const float2*)f0;
        const float2* f12 = (const float2*)f1;
        const float2* f22 = (const float2*)f2;
        float2* o2 = (float2*)o;
        for (int c = lane; c < C / 2; c += 32) {
            float2 a = f02[c], b = f12[c], d = f22[c];
            float vx = __fadd_rn(__fadd_rn(__fmul_rn(e0, a.x), __fmul_rn(e1, b.x)),
                                 __fmul_rn(e2, d.x));
            float vy = __fadd_rn(__fadd_rn(__fmul_rn(e0, a.y), __fmul_rn(e1, b.y)),
                                 __fmul_rn(e2, d.y));
            o2[c] = make_float2(vx, vy);
        }
    } else {
        for (int c = lane; c < C; c += 32) {
            float val = __fadd_rn(__fadd_rn(__fmul_rn(e0, f0[c]),
                                            __fmul_rn(e1, f1[c])),
                                  __fmul_rn(e2, f2[c]));
            o[c] = val;
        }
    }
}

// ------------------------- launch -----------------------------------------
extern "C" void kernel_launch(void* const* d_in, const int* in_sizes, int n_in,
                              void* d_out, int out_size)
{
    const float* positions = (const float*)d_in[0];
    const float* features  = (const float*)d_in[1];
    const int*   faces     = (const int*)d_in[2];
    const float* K         = (const float*)d_in[3];
    const float* RT        = (const float*)d_in[4];

    int V  = in_sizes[0] / 3;
    int C  = in_sizes[1] / V;
    int Fn = in_sizes[2] / 3;
    int npix = out_size / (C + 6);
    int W = (int)(sqrt((double)npix) + 0.5);
    if (W <= 0) W = 1;
    int H = npix / W;
    float* out = (float*)d_out;

    int tilesX = (W + TILE - 1) / TILE;
    int tilesY = (H + TILE - 1) / TILE;
    int ntiles = tilesX * tilesY;

    k_face<<<(Fn + 127) / 128, 128>>>(positions, K, RT, faces, Fn, npix,
                                      (float)W, (float)H);
    k_scan<<<1, NBUCK>>>();
    k_scatter<<<(Fn + 127) / 128, 128>>>(Fn);

    dim3 rg(ntiles, NSPLIT);
    k_raster<<<rg, 256>>>(W, H, npix, tilesX);

    k_mf<<<(npix * 32 + 255) / 256, 256>>>(out, features, faces, W, H, npix, C);
}